// round 9
// baseline (speedup 1.0000x reference)
#include <cuda_runtime.h>
#include <cuda_bf16.h>

#define NBOUND 19            // NUM_BINS - 1 boundaries per code
#define NBINS  20
#define ED     768
#define V4     192           // float4 per row
#define COLS_PER_LANE 6      // 192 / 32
#define ROWS_PER_WARP 2
#define WARPS_PER_CTA 8
#define TPB   (32 * WARPS_PER_CTA)   // 256
#define ROWS_PER_CTA (WARPS_PER_CTA * ROWS_PER_WARP)  // 16

struct RowParams {
    float a, na;
    int   lower, upper;
    bool  interior;
};

// Per-row scalar parameters; all lanes end up with uniform values.
// bj must already be loaded (lane<19 holds boundary[lane], else +inf).
__device__ __forceinline__ RowParams row_params(float v, float bj) {
    const unsigned m = __ballot_sync(0xffffffffu, bj < v);
    const int idx = __popc(m);                    // searchsorted left, [0,19]

    const int lo_i = min(max(idx - 1, 0), NBOUND - 1);
    const int hi_i = min(idx, NBOUND - 1);
    const float lo_b = __shfl_sync(0xffffffffu, bj, lo_i);
    const float hi_b = __shfl_sync(0xffffffffu, bj, hi_i);

    RowParams p;
    p.interior = (idx > 0) && (idx < NBINS - 1);
    const float denom = hi_b - lo_b;
    float a;
    if (fabsf(denom) < 1e-8f) a = 0.5f;
    else a = fminf(fmaxf((v - lo_b) / denom, 0.0f), 1.0f);
    if (!p.interior) a = 0.0f;
    p.a = a;
    p.na = 1.0f - a;
    p.lower = (idx == 0) ? 0 : ((idx >= NBINS - 1) ? (NBINS - 1) : idx - 1);
    p.upper = p.interior ? idx : p.lower;
    return p;
}

__global__ __launch_bounds__(TPB) void sde_kernel(
    const float* __restrict__ values,
    const int*   __restrict__ code_ids,
    const float* __restrict__ boundaries,
    const float4* __restrict__ embed,
    float4* __restrict__ out,
    int batch)
{
    const int lane = threadIdx.x & 31;
    const int wid  = threadIdx.x >> 5;
    const int rowA = (blockIdx.x * WARPS_PER_CTA + wid) * ROWS_PER_WARP;
    const int rowB = rowA + 1;
    if (rowA >= batch) return;
    const bool haveB = (rowB < batch);

    // ---- scalar phase: both rows' dependent chains issued together ----
    const float vA = __ldg(values + rowA);
    const float vB = haveB ? __ldg(values + rowB) : 0.0f;
    const int   cA = __ldg(code_ids + rowA);
    const int   cB = haveB ? __ldg(code_ids + rowB) : 0;

    float bjA = 3.0e38f, bjB = 3.0e38f;
    if (lane < NBOUND) {
        bjA = __ldg(boundaries + (size_t)cA * NBOUND + lane);
        bjB = __ldg(boundaries + (size_t)cB * NBOUND + lane);
    }

    const RowParams pA = row_params(vA, bjA);
    const RowParams pB = row_params(vB, bjB);

    // ---- streaming phase: 2 rows x 6 float4 columns per lane ----
    const float4* loA = embed + (size_t)pA.lower * V4;
    const float4* upA = embed + (size_t)pA.upper * V4;
    const float4* loB = embed + (size_t)pB.lower * V4;
    const float4* upB = embed + (size_t)pB.upper * V4;
    float4* outA = out + (size_t)rowA * V4;
    float4* outB = out + (size_t)rowB * V4;

    if (pA.interior && (haveB && pB.interior)) {
        // common path: full lerp for both rows
#pragma unroll
        for (int j = 0; j < COLS_PER_LANE; j++) {
            const int col = j * 32 + lane;
            const float4 la = __ldg(loA + col);
            const float4 ua = __ldg(upA + col);
            const float4 lb = __ldg(loB + col);
            const float4 ub = __ldg(upB + col);
            float4 oa, ob;
            oa.x = pA.na * la.x + pA.a * ua.x;
            oa.y = pA.na * la.y + pA.a * ua.y;
            oa.z = pA.na * la.z + pA.a * ua.z;
            oa.w = pA.na * la.w + pA.a * ua.w;
            ob.x = pB.na * lb.x + pB.a * ub.x;
            ob.y = pB.na * lb.y + pB.a * ub.y;
            ob.z = pB.na * lb.z + pB.a * ub.z;
            ob.w = pB.na * lb.w + pB.a * ub.w;
            outA[col] = oa;
            outB[col] = ob;
        }
    } else {
        // at least one row is a pure copy (a==0, lower==upper): per-row paths
#pragma unroll
        for (int j = 0; j < COLS_PER_LANE; j++) {
            const int col = j * 32 + lane;
            float4 oa;
            if (pA.interior) {
                const float4 la = __ldg(loA + col);
                const float4 ua = __ldg(upA + col);
                oa.x = pA.na * la.x + pA.a * ua.x;
                oa.y = pA.na * la.y + pA.a * ua.y;
                oa.z = pA.na * la.z + pA.a * ua.z;
                oa.w = pA.na * la.w + pA.a * ua.w;
            } else {
                oa = __ldg(loA + col);
            }
            outA[col] = oa;
            if (haveB) {
                float4 ob;
                if (pB.interior) {
                    const float4 lb = __ldg(loB + col);
                    const float4 ub = __ldg(upB + col);
                    ob.x = pB.na * lb.x + pB.a * ub.x;
                    ob.y = pB.na * lb.y + pB.a * ub.y;
                    ob.z = pB.na * lb.z + pB.a * ub.z;
                    ob.w = pB.na * lb.w + pB.a * ub.w;
                } else {
                    ob = __ldg(loB + col);
                }
                outB[col] = ob;
            }
        }
    }
}

extern "C" void kernel_launch(void* const* d_in, const int* in_sizes, int n_in,
                              void* d_out, int out_size) {
    const float*  values     = (const float*)d_in[0];
    const int*    code_ids   = (const int*)d_in[1];
    const float*  boundaries = (const float*)d_in[2];
    const float4* embed      = (const float4*)d_in[3];
    float4* out = (float4*)d_out;

    const int batch = in_sizes[0];   // 131072 rows
    const int grid  = (batch + ROWS_PER_CTA - 1) / ROWS_PER_CTA;
    sde_kernel<<<grid, TPB>>>(values, code_ids, boundaries, embed, out, batch);
}